// round 13
// baseline (speedup 1.0000x reference)
#include <cuda_runtime.h>
#include <math.h>

// ---------------- problem constants ----------------
#define T_STEPS 64
#define B_SZ    128
#define M_COLS  1000
#define N_CELLS 4
#define TC      4000      // M_COLS * N_CELLS
#define K_TOP   25
#define D_IN    1024
#define D_OUT   1024
#define GEMM_BLOCKS 512   // 64 timesteps x 8 column tiles
#define DEC_BLOCKS  ((T_STEPS * B_SZ) / 2)   // 4096, 2 output rows per block

// ---------------- persistent device state ----------------
__device__ float g_za_all[T_STEPS * B_SZ * M_COLS]; // feedforward drive
__device__ float g_wbt  [TC * TC];                  // w_b transposed
__device__ float g_wdt  [M_COLS * D_OUT];           // w_d transposed
__device__ int   g_ycidx[T_STEPS * B_SZ * K_TOP];   // selected columns per (t,b)
__device__ float g_ycval[T_STEPS * B_SZ * K_TOP];   // max(y,0) per (t,b)
__device__ int   g_cnt  [T_STEPS];                  // za readiness counters
__device__ int   g_ready[T_STEPS];                  // (t,b) emit counters (128 = all b)

// ---------------- init (counters must reset every graph replay) ----------------
__global__ void zero_cnt_kernel() {
    if (threadIdx.x < T_STEPS)            g_cnt  [threadIdx.x] = 0;
    else if (threadIdx.x < 2 * T_STEPS)   g_ready[threadIdx.x - T_STEPS] = 0;
}

// ---------------- generic 32x32 tiled transpose with bounds ----------------
__global__ void transpose_kernel(const float* __restrict__ in, float* __restrict__ out,
                                 int rows, int cols)
{
    __shared__ float tile[32][33];
    int c0 = blockIdx.x * 32, r0 = blockIdx.y * 32;
#pragma unroll
    for (int j = 0; j < 32; j += 8) {
        int r = r0 + threadIdx.y + j, c = c0 + threadIdx.x;
        if (r < rows && c < cols)
            tile[threadIdx.y + j][threadIdx.x] = in[(size_t)r * cols + c];
    }
    __syncthreads();
#pragma unroll
    for (int j = 0; j < 32; j += 8) {
        int c = c0 + threadIdx.y + j, r = r0 + threadIdx.x;
        if (r < rows && c < cols)
            out[(size_t)c * rows + r] = tile[threadIdx.x][threadIdx.y + j];
    }
}

// ---------------- helpers ----------------
__device__ __forceinline__ unsigned int ord_key(float f) {
    unsigned int u = __float_as_uint(f);
    return (u & 0x80000000u) ? ~u : (u | 0x80000000u);
}

// ---------------- shared memory overlays ----------------
struct GemmSmem {                       // 34,304 B
    float As[2][16][128 + 4];
    float Bs[2][16][128 + 8];
};
struct ScanSmem {                       // ~29.2 KB
    float         psi[TC];
    float         lam[M_COLS];
    float         sig[M_COLS];
    unsigned char win[M_COLS];
    int           didx [K_TOP];
    float         delta[K_TOP];
};

// ---------------- GEMM part: one 128x128 za tile, then signal ----------------
__device__ void gemm_part(const float* __restrict__ x, const float* __restrict__ w_a,
                          char* smem, int gbid)
{
    GemmSmem* S = reinterpret_cast<GemmSmem*>(smem);
    const int t   = gbid >> 3;
    const int n0  = (gbid & 7) * 128;
    const int tid = threadIdx.x;
    const int tn  = tid & 31;
    const int tm  = tid >> 5;
    const int arow = tid >> 2, aq = tid & 3;

    const float* A = x + (size_t)t * B_SZ * D_IN;
    float*       C = g_za_all + (size_t)t * B_SZ * M_COLS;

    unsigned long long acc[8][2];
#pragma unroll
    for (int i = 0; i < 8; i++) { acc[i][0] = 0ull; acc[i][1] = 0ull; }

    float4 aR = *reinterpret_cast<const float4*>(&A[(size_t)arow * D_IN + aq * 4]);
    float4 bR = make_float4(0.f, 0.f, 0.f, 0.f);
    if (n0 + arow < M_COLS)
        bR = *reinterpret_cast<const float4*>(&w_a[(size_t)(n0 + arow) * D_IN + aq * 4]);
    {
        S->As[0][aq * 4 + 0][arow] = aR.x; S->As[0][aq * 4 + 1][arow] = aR.y;
        S->As[0][aq * 4 + 2][arow] = aR.z; S->As[0][aq * 4 + 3][arow] = aR.w;
        S->Bs[0][aq * 4 + 0][arow] = bR.x; S->Bs[0][aq * 4 + 1][arow] = bR.y;
        S->Bs[0][aq * 4 + 2][arow] = bR.z; S->Bs[0][aq * 4 + 3][arow] = bR.w;
    }
    __syncthreads();

    const int nk = D_IN / 16;
    for (int kt = 0; kt < nk; kt++) {
        const int buf = kt & 1;
        if (kt + 1 < nk) {
            int kb = (kt + 1) * 16;
            aR = *reinterpret_cast<const float4*>(&A[(size_t)arow * D_IN + kb + aq * 4]);
            bR = make_float4(0.f, 0.f, 0.f, 0.f);
            if (n0 + arow < M_COLS)
                bR = *reinterpret_cast<const float4*>(&w_a[(size_t)(n0 + arow) * D_IN + kb + aq * 4]);
        }
#pragma unroll
        for (int k = 0; k < 16; k++) {
            float4 a0 = *reinterpret_cast<const float4*>(&S->As[buf][k][tm * 8]);
            float4 a1 = *reinterpret_cast<const float4*>(&S->As[buf][k][tm * 8 + 4]);
            const unsigned long long* bp =
                reinterpret_cast<const unsigned long long*>(&S->Bs[buf][k][tn * 4]);
            unsigned long long b2[2] = {bp[0], bp[1]};
            float av[8] = {a0.x, a0.y, a0.z, a0.w, a1.x, a1.y, a1.z, a1.w};
#pragma unroll
            for (int i = 0; i < 8; i++) {
                unsigned int au = __float_as_uint(av[i]);
                unsigned long long ap;
                asm("mov.b64 %0, {%1, %1};" : "=l"(ap) : "r"(au));
                asm("fma.rn.f32x2 %0, %1, %2, %0;" : "+l"(acc[i][0]) : "l"(ap), "l"(b2[0]));
                asm("fma.rn.f32x2 %0, %1, %2, %0;" : "+l"(acc[i][1]) : "l"(ap), "l"(b2[1]));
            }
        }
        if (kt + 1 < nk) {
            const int nb = buf ^ 1;
            S->As[nb][aq * 4 + 0][arow] = aR.x; S->As[nb][aq * 4 + 1][arow] = aR.y;
            S->As[nb][aq * 4 + 2][arow] = aR.z; S->As[nb][aq * 4 + 3][arow] = aR.w;
            S->Bs[nb][aq * 4 + 0][arow] = bR.x; S->Bs[nb][aq * 4 + 1][arow] = bR.y;
            S->Bs[nb][aq * 4 + 2][arow] = bR.z; S->Bs[nb][aq * 4 + 3][arow] = bR.w;
            __syncthreads();
        }
    }

#pragma unroll
    for (int i = 0; i < 8; i++) {
        int gm = tm * 8 + i;
#pragma unroll
        for (int j = 0; j < 2; j++) {
            unsigned int lo, hi;
            asm("mov.b64 {%0, %1}, %2;" : "=r"(lo), "=r"(hi) : "l"(acc[i][j]));
            int gn = n0 + tn * 4 + 2 * j;
            if (gn < M_COLS)     C[(size_t)gm * M_COLS + gn]     = __uint_as_float(lo);
            if (gn + 1 < M_COLS) C[(size_t)gm * M_COLS + gn + 1] = __uint_as_float(hi);
        }
    }

    __threadfence();
    __syncthreads();
    if (threadIdx.x == 0) atomicAdd(&g_cnt[t], 1);
}

// ---------------- scan part (R9 structure + fast top-k + ready signal) --------
__device__ void scan_part(char* smem, int b)
{
    ScanSmem* S = reinterpret_cast<ScanSmem*>(smem);
    const int tid    = threadIdx.x;
    const int lane   = tid & 31;
    const int warpid = tid >> 5;

    const int c0 = tid;                // column 0..511
    const int c1 = tid + 512;          // column 512..1023 (valid < 1000)
    const bool two = (c1 < M_COLS);

    float4 z0 = make_float4(0.f, 0.f, 0.f, 0.f);
    float4 z1 = make_float4(0.f, 0.f, 0.f, 0.f);

    for (int i = tid; i < TC; i += 512) S->psi[i] = 0.f;
    __syncthreads();

    for (int t = 0; t < T_STEPS; t++) {
        // wait for za[t] (8 tiles)
        if (tid == 0) {
            unsigned int v;
            do {
                asm volatile("ld.acquire.gpu.u32 %0, [%1];"
                             : "=r"(v) : "l"(&g_cnt[t]) : "memory");
            } while (v < 8u);
        }
        __syncthreads();

        // ---- fused: rank-25 z_b update (t>0), fully unrolled (high MLP) ----
        if (t > 0) {
            float4 a0 = make_float4(0.5f * z0.x, 0.5f * z0.y, 0.5f * z0.z, 0.5f * z0.w);
            float4 a1 = make_float4(0.5f * z1.x, 0.5f * z1.y, 0.5f * z1.z, 0.5f * z1.w);
#pragma unroll
            for (int i = 0; i < K_TOP; i++) {
                float d = S->delta[i];
                const float* base = &g_wbt[(size_t)S->didx[i] * TC];
                float4 w0 = *reinterpret_cast<const float4*>(&base[c0 * 4]);
                a0.x = fmaf(d, w0.x, a0.x); a0.y = fmaf(d, w0.y, a0.y);
                a0.z = fmaf(d, w0.z, a0.z); a0.w = fmaf(d, w0.w, a0.w);
                if (two) {
                    float4 w1 = *reinterpret_cast<const float4*>(&base[c1 * 4]);
                    a1.x = fmaf(d, w1.x, a1.x); a1.y = fmaf(d, w1.y, a1.y);
                    a1.z = fmaf(d, w1.z, a1.z); a1.w = fmaf(d, w1.w, a1.w);
                }
            }
            z0 = a0; z1 = a1;
        }

        // ---- phase A: winner cell + column max of pi + psi decay ----
        const float* zab = g_za_all + ((size_t)t * B_SZ + b) * M_COLS;
#pragma unroll
        for (int h = 0; h < 2; h++) {
            int c = (h == 0) ? c0 : c1;
            if (h == 1 && !two) break;
            float4 z = (h == 0) ? z0 : z1;
            float  zac = __ldcg(&zab[c]);
            float4 ph  = *reinterpret_cast<const float4*>(&S->psi[c * 4]);
            float sig[4] = {zac + z.x, zac + z.y, zac + z.z, zac + z.w};
            float pv [4] = {sig[0] * (1.f - ph.x), sig[1] * (1.f - ph.y),
                            sig[2] * (1.f - ph.z), sig[3] * (1.f - ph.w)};
            float best = pv[0]; int bw = 0;
#pragma unroll
            for (int n = 1; n < N_CELLS; n++)
                if (pv[n] > best) { best = pv[n]; bw = n; }
            S->lam[c] = best;
            S->win[c] = (unsigned char)bw;
            S->sig[c] = sig[bw];
            *reinterpret_cast<float4*>(&S->psi[c * 4]) =
                make_float4(0.5f * ph.x, 0.5f * ph.y, 0.5f * ph.z, 0.5f * ph.w);
        }
        __syncthreads();

        // ---- top-K by warp 0: per-lane top-2 cache + REDUX extraction ----
        if (warpid == 0) {
            float m1 = -INFINITY, m2 = -INFINITY;
            int   i1 = 0x7fffffff, i2 = 0x7fffffff;
#pragma unroll
            for (int j = 0; j < 32; j++) {
                int col = j * 32 + lane;
                float v = (col < M_COLS) ? S->lam[col] : -INFINITY;
                if (v > m1)      { m2 = m1; i2 = i1; m1 = v; i1 = col; }
                else if (v > m2) { m2 = v;  i2 = col; }
            }
            int mycol = 0;
            for (int it = 0; it < K_TOP; it++) {
                unsigned int key  = ord_key(m1);
                unsigned int kmax = __reduce_max_sync(0xffffffffu, key);
                unsigned int cand = (key == kmax) ? (unsigned int)i1 : 0x7fffffffu;
                int c = (int)__reduce_min_sync(0xffffffffu, cand);
                if (lane == it) mycol = c;
                if ((c & 31) == lane) {        // owning lane: remove + refresh cache
                    S->lam[c] = -INFINITY;
                    m1 = m2; i1 = i2;
                    if (it < K_TOP - 1) {
                        float a = -INFINITY, bb = -INFINITY;
                        int   aj = 0x7fffffff, bj = 0x7fffffff;
#pragma unroll
                        for (int j = 0; j < 32; j++) {
                            int col = j * 32 + lane;
                            float v = (col < M_COLS) ? S->lam[col] : -INFINITY;
                            if (v > a)       { bb = a; bj = aj; a = v; aj = col; }
                            else if (v > bb) { bb = v; bj = col; }
                        }
                        if (aj == i1) { m2 = bb; i2 = bj; }
                        else          { m2 = a;  i2 = aj; }
                    }
                }
            }
            __syncwarp();

            // ---- emit: lanes 0..24, one winner each (psi already decayed) ----
            if (lane < K_TOP) {
                int   c    = mycol;
                int   w    = (int)S->win[c];
                int   cell = c * N_CELLS + w;
                float y    = tanhf(S->sig[c]);
                float pd   = S->psi[cell];
                S->didx [lane] = cell;
                S->delta[lane] = fmaxf(y - pd, 0.f);
                S->psi[cell]   = fmaxf(pd, y);
                size_t o = ((size_t)t * B_SZ + b) * K_TOP + lane;
                g_ycidx[o] = c;
                g_ycval[o] = fmaxf(y, 0.f);
            }
            __threadfence();                   // make ycidx/ycval gpu-visible
        }
        __syncthreads();

        // signal decode: this (t,b) emitted (release-add, warp 1 lane 0)
        if (tid == 32) {
            asm volatile("red.release.gpu.global.add.u32 [%0], %1;"
                         :: "l"(&g_ready[t]), "r"(1u) : "memory");
        }
    }
}

// ---------------- decode part: 2 output rows per block, gated on g_ready ------
__device__ void decode_part(const float* __restrict__ b_d, float* __restrict__ out,
                            char* smem, int dbid)
{
    int*   s_c = reinterpret_cast<int*>(smem);           // [2][32] (padded)
    float* s_y = reinterpret_cast<float*>(smem) + 64;    // [2][32]
    const int tid  = threadIdx.x;
    const int half = tid >> 8;         // 0 or 1
    const int r    = tid & 255;
    const int tb   = dbid * 2 + half;
    const int t    = tb >> 7;          // same for both halves (128 rows per t)

    if (tid == 0) {
        unsigned int v;
        do {
            asm volatile("ld.acquire.gpu.u32 %0, [%1];"
                         : "=r"(v) : "l"(&g_ready[t]) : "memory");
        } while (v < (unsigned)B_SZ);
    }
    __syncthreads();

    if (r < K_TOP) {
        s_c[half * 32 + r] = g_ycidx[(size_t)tb * K_TOP + r];
        s_y[half * 32 + r] = g_ycval[(size_t)tb * K_TOP + r];
    }
    __syncthreads();

    float4 acc = *reinterpret_cast<const float4*>(&b_d[r * 4]);
#pragma unroll
    for (int i = 0; i < K_TOP; i++) {
        float y = s_y[half * 32 + i];
        const float4 w = *reinterpret_cast<const float4*>(
            &g_wdt[(size_t)s_c[half * 32 + i] * D_OUT + r * 4]);
        acc.x = fmaf(y, w.x, acc.x);
        acc.y = fmaf(y, w.y, acc.y);
        acc.z = fmaf(y, w.z, acc.z);
        acc.w = fmaf(y, w.w, acc.w);
    }
    *reinterpret_cast<float4*>(&out[(size_t)tb * D_OUT + r * 4]) = acc;
}

// ---------------- fused kernel: scan blocks, then GEMM, then decode ----------
__global__ void __launch_bounds__(512, 2)
fused_all(const float* __restrict__ x, const float* __restrict__ w_a,
          const float* __restrict__ b_d, float* __restrict__ out)
{
    __shared__ __align__(16) char smem[sizeof(GemmSmem)];
    if (blockIdx.x < B_SZ)
        scan_part(smem, blockIdx.x);
    else if (blockIdx.x < B_SZ + GEMM_BLOCKS)
        gemm_part(x, w_a, smem, blockIdx.x - B_SZ);
    else
        decode_part(b_d, out, smem, blockIdx.x - (B_SZ + GEMM_BLOCKS));
}

// ---------------- host launch ----------------
extern "C" void kernel_launch(void* const* d_in, const int* in_sizes, int n_in,
                              void* d_out, int out_size)
{
    const float* x   = (const float*)d_in[0];   // [T, B, D_IN]
    const float* w_a = (const float*)d_in[1];   // [M, D_IN]
    const float* w_b = (const float*)d_in[2];   // [TC, TC]
    const float* w_d = (const float*)d_in[3];   // [D_OUT, M]
    const float* b_d = (const float*)d_in[4];   // [D_OUT]
    float* out = (float*)d_out;                 // [T, B, D_OUT]

    float *wbt, *wdt;
    cudaGetSymbolAddress((void**)&wbt, g_wbt);
    cudaGetSymbolAddress((void**)&wdt, g_wdt);

    zero_cnt_kernel<<<1, 128>>>();

    transpose_kernel<<<dim3(TC / 32, TC / 32), dim3(32, 8)>>>(w_b, wbt, TC, TC);
    transpose_kernel<<<dim3((M_COLS + 31) / 32, D_OUT / 32), dim3(32, 8)>>>(
        w_d, wdt, D_OUT, M_COLS);

    // scan (128, first) + GEMM (512) + decode (4096) in one kernel
    fused_all<<<B_SZ + GEMM_BLOCKS + DEC_BLOCKS, 512>>>(x, w_a, b_d, out);
}

// round 14
// speedup vs baseline: 1.0306x; 1.0306x over previous
#include <cuda_runtime.h>
#include <math.h>

// ---------------- problem constants ----------------
#define T_STEPS 64
#define B_SZ    128
#define M_COLS  1000
#define N_CELLS 4
#define TC      4000      // M_COLS * N_CELLS
#define K_TOP   25
#define D_IN    1024
#define D_OUT   1024
#define GEMM_BLOCKS 512   // 64 timesteps x 8 column tiles

// ---------------- persistent device state ----------------
__device__ float g_za_all[T_STEPS * B_SZ * M_COLS]; // feedforward drive
__device__ float g_wbt  [TC * TC];                  // w_b transposed
__device__ float g_wdt  [M_COLS * D_OUT];           // w_d transposed
__device__ int   g_ycidx[T_STEPS * B_SZ * K_TOP];   // selected columns per (t,b)
__device__ float g_ycval[T_STEPS * B_SZ * K_TOP];   // max(y,0) per (t,b)
__device__ int   g_cnt  [T_STEPS];                  // za readiness counters

// ---------------- init (counters must reset every graph replay) ----------------
__global__ void zero_cnt_kernel() {
    if (threadIdx.x < T_STEPS) g_cnt[threadIdx.x] = 0;
}

// ---------------- generic 32x32 tiled transpose with bounds ----------------
__global__ void transpose_kernel(const float* __restrict__ in, float* __restrict__ out,
                                 int rows, int cols)
{
    __shared__ float tile[32][33];
    int c0 = blockIdx.x * 32, r0 = blockIdx.y * 32;
#pragma unroll
    for (int j = 0; j < 32; j += 8) {
        int r = r0 + threadIdx.y + j, c = c0 + threadIdx.x;
        if (r < rows && c < cols)
            tile[threadIdx.y + j][threadIdx.x] = in[(size_t)r * cols + c];
    }
    __syncthreads();
#pragma unroll
    for (int j = 0; j < 32; j += 8) {
        int c = c0 + threadIdx.y + j, r = r0 + threadIdx.x;
        if (r < rows && c < cols)
            out[(size_t)c * rows + r] = tile[threadIdx.x][threadIdx.y + j];
    }
}

// ---------------- helpers ----------------
__device__ __forceinline__ unsigned int ord_key(float f) {
    unsigned int u = __float_as_uint(f);
    return (u & 0x80000000u) ? ~u : (u | 0x80000000u);
}

// ---------------- shared memory overlays ----------------
struct GemmSmem {                       // 34,304 B
    float As[2][16][128 + 4];
    float Bs[2][16][128 + 8];
};
struct ScanSmem {                       // ~29.2 KB
    float         psi[TC];
    float         lam[M_COLS];
    float         sig[M_COLS];
    unsigned char win[M_COLS];
    int           didx [K_TOP];
    float         delta[K_TOP];
};

// ---------------- GEMM part: one 128x128 za tile, then signal ----------------
__device__ void gemm_part(const float* __restrict__ x, const float* __restrict__ w_a,
                          char* smem, int gbid)
{
    GemmSmem* S = reinterpret_cast<GemmSmem*>(smem);
    const int t   = gbid >> 3;
    const int n0  = (gbid & 7) * 128;
    const int tid = threadIdx.x;
    const int tn  = tid & 31;
    const int tm  = tid >> 5;
    const int arow = tid >> 2, aq = tid & 3;

    const float* A = x + (size_t)t * B_SZ * D_IN;
    float*       C = g_za_all + (size_t)t * B_SZ * M_COLS;

    unsigned long long acc[8][2];
#pragma unroll
    for (int i = 0; i < 8; i++) { acc[i][0] = 0ull; acc[i][1] = 0ull; }

    float4 aR = *reinterpret_cast<const float4*>(&A[(size_t)arow * D_IN + aq * 4]);
    float4 bR = make_float4(0.f, 0.f, 0.f, 0.f);
    if (n0 + arow < M_COLS)
        bR = *reinterpret_cast<const float4*>(&w_a[(size_t)(n0 + arow) * D_IN + aq * 4]);
    {
        S->As[0][aq * 4 + 0][arow] = aR.x; S->As[0][aq * 4 + 1][arow] = aR.y;
        S->As[0][aq * 4 + 2][arow] = aR.z; S->As[0][aq * 4 + 3][arow] = aR.w;
        S->Bs[0][aq * 4 + 0][arow] = bR.x; S->Bs[0][aq * 4 + 1][arow] = bR.y;
        S->Bs[0][aq * 4 + 2][arow] = bR.z; S->Bs[0][aq * 4 + 3][arow] = bR.w;
    }
    __syncthreads();

    const int nk = D_IN / 16;
    for (int kt = 0; kt < nk; kt++) {
        const int buf = kt & 1;
        if (kt + 1 < nk) {
            int kb = (kt + 1) * 16;
            aR = *reinterpret_cast<const float4*>(&A[(size_t)arow * D_IN + kb + aq * 4]);
            bR = make_float4(0.f, 0.f, 0.f, 0.f);
            if (n0 + arow < M_COLS)
                bR = *reinterpret_cast<const float4*>(&w_a[(size_t)(n0 + arow) * D_IN + kb + aq * 4]);
        }
#pragma unroll
        for (int k = 0; k < 16; k++) {
            float4 a0 = *reinterpret_cast<const float4*>(&S->As[buf][k][tm * 8]);
            float4 a1 = *reinterpret_cast<const float4*>(&S->As[buf][k][tm * 8 + 4]);
            const unsigned long long* bp =
                reinterpret_cast<const unsigned long long*>(&S->Bs[buf][k][tn * 4]);
            unsigned long long b2[2] = {bp[0], bp[1]};
            float av[8] = {a0.x, a0.y, a0.z, a0.w, a1.x, a1.y, a1.z, a1.w};
#pragma unroll
            for (int i = 0; i < 8; i++) {
                unsigned int au = __float_as_uint(av[i]);
                unsigned long long ap;
                asm("mov.b64 %0, {%1, %1};" : "=l"(ap) : "r"(au));
                asm("fma.rn.f32x2 %0, %1, %2, %0;" : "+l"(acc[i][0]) : "l"(ap), "l"(b2[0]));
                asm("fma.rn.f32x2 %0, %1, %2, %0;" : "+l"(acc[i][1]) : "l"(ap), "l"(b2[1]));
            }
        }
        if (kt + 1 < nk) {
            const int nb = buf ^ 1;
            S->As[nb][aq * 4 + 0][arow] = aR.x; S->As[nb][aq * 4 + 1][arow] = aR.y;
            S->As[nb][aq * 4 + 2][arow] = aR.z; S->As[nb][aq * 4 + 3][arow] = aR.w;
            S->Bs[nb][aq * 4 + 0][arow] = bR.x; S->Bs[nb][aq * 4 + 1][arow] = bR.y;
            S->Bs[nb][aq * 4 + 2][arow] = bR.z; S->Bs[nb][aq * 4 + 3][arow] = bR.w;
            __syncthreads();
        }
    }

#pragma unroll
    for (int i = 0; i < 8; i++) {
        int gm = tm * 8 + i;
#pragma unroll
        for (int j = 0; j < 2; j++) {
            unsigned int lo, hi;
            asm("mov.b64 {%0, %1}, %2;" : "=r"(lo), "=r"(hi) : "l"(acc[i][j]));
            int gn = n0 + tn * 4 + 2 * j;
            if (gn < M_COLS)     C[(size_t)gm * M_COLS + gn]     = __uint_as_float(lo);
            if (gn + 1 < M_COLS) C[(size_t)gm * M_COLS + gn + 1] = __uint_as_float(hi);
        }
    }

    __threadfence();
    __syncthreads();
    if (threadIdx.x == 0) atomicAdd(&g_cnt[t], 1);
}

// ---------------- scan part: R9 structure, faster top-k ----------------
__device__ void scan_part(char* smem, int b)
{
    ScanSmem* S = reinterpret_cast<ScanSmem*>(smem);
    const int tid    = threadIdx.x;
    const int lane   = tid & 31;
    const int warpid = tid >> 5;

    const int c0 = tid;                // column 0..511
    const int c1 = tid + 512;          // column 512..1023 (valid < 1000)
    const bool two = (c1 < M_COLS);

    float4 z0 = make_float4(0.f, 0.f, 0.f, 0.f);
    float4 z1 = make_float4(0.f, 0.f, 0.f, 0.f);

    for (int i = tid; i < TC; i += 512) S->psi[i] = 0.f;
    __syncthreads();

    for (int t = 0; t < T_STEPS; t++) {
        // wait for za[t] (8 tiles)
        if (tid == 0) {
            unsigned int v;
            do {
                asm volatile("ld.acquire.gpu.u32 %0, [%1];"
                             : "=r"(v) : "l"(&g_cnt[t]) : "memory");
            } while (v < 8u);
        }
        __syncthreads();

        // ---- fused: rank-25 z_b update (t>0), fully unrolled (high MLP) ----
        if (t > 0) {
            float4 a0 = make_float4(0.5f * z0.x, 0.5f * z0.y, 0.5f * z0.z, 0.5f * z0.w);
            float4 a1 = make_float4(0.5f * z1.x, 0.5f * z1.y, 0.5f * z1.z, 0.5f * z1.w);
#pragma unroll
            for (int i = 0; i < K_TOP; i++) {
                float d = S->delta[i];
                const float* base = &g_wbt[(size_t)S->didx[i] * TC];
                float4 w0 = *reinterpret_cast<const float4*>(&base[c0 * 4]);
                a0.x = fmaf(d, w0.x, a0.x); a0.y = fmaf(d, w0.y, a0.y);
                a0.z = fmaf(d, w0.z, a0.z); a0.w = fmaf(d, w0.w, a0.w);
                if (two) {
                    float4 w1 = *reinterpret_cast<const float4*>(&base[c1 * 4]);
                    a1.x = fmaf(d, w1.x, a1.x); a1.y = fmaf(d, w1.y, a1.y);
                    a1.z = fmaf(d, w1.z, a1.z); a1.w = fmaf(d, w1.w, a1.w);
                }
            }
            z0 = a0; z1 = a1;
        }

        // ---- phase A: winner cell + column max of pi + psi decay ----
        const float* zab = g_za_all + ((size_t)t * B_SZ + b) * M_COLS;
#pragma unroll
        for (int h = 0; h < 2; h++) {
            int c = (h == 0) ? c0 : c1;
            if (h == 1 && !two) break;
            float4 z = (h == 0) ? z0 : z1;
            float  zac = __ldcg(&zab[c]);
            float4 ph  = *reinterpret_cast<const float4*>(&S->psi[c * 4]);
            float sig[4] = {zac + z.x, zac + z.y, zac + z.z, zac + z.w};
            float pv [4] = {sig[0] * (1.f - ph.x), sig[1] * (1.f - ph.y),
                            sig[2] * (1.f - ph.z), sig[3] * (1.f - ph.w)};
            float best = pv[0]; int bw = 0;
#pragma unroll
            for (int n = 1; n < N_CELLS; n++)
                if (pv[n] > best) { best = pv[n]; bw = n; }
            S->lam[c] = best;
            S->win[c] = (unsigned char)bw;
            S->sig[c] = sig[bw];
            *reinterpret_cast<float4*>(&S->psi[c * 4]) =
                make_float4(0.5f * ph.x, 0.5f * ph.y, 0.5f * ph.z, 0.5f * ph.w);
        }
        __syncthreads();

        // ---- top-K by warp 0: per-lane top-2 cache + REDUX extraction ----
        if (warpid == 0) {
            float m1 = -INFINITY, m2 = -INFINITY;
            int   i1 = 0x7fffffff, i2 = 0x7fffffff;
#pragma unroll
            for (int j = 0; j < 32; j++) {
                int col = j * 32 + lane;
                float v = (col < M_COLS) ? S->lam[col] : -INFINITY;
                if (v > m1)      { m2 = m1; i2 = i1; m1 = v; i1 = col; }
                else if (v > m2) { m2 = v;  i2 = col; }
            }
            int mycol = 0;
            for (int it = 0; it < K_TOP; it++) {
                unsigned int key  = ord_key(m1);
                unsigned int kmax = __reduce_max_sync(0xffffffffu, key);
                unsigned int cand = (key == kmax) ? (unsigned int)i1 : 0x7fffffffu;
                int c = (int)__reduce_min_sync(0xffffffffu, cand);
                if (lane == it) mycol = c;
                if ((c & 31) == lane) {        // owning lane: remove + refresh cache
                    S->lam[c] = -INFINITY;
                    m1 = m2; i1 = i2;
                    if (it < K_TOP - 1) {
                        float a = -INFINITY, bb = -INFINITY;
                        int   aj = 0x7fffffff, bj = 0x7fffffff;
#pragma unroll
                        for (int j = 0; j < 32; j++) {
                            int col = j * 32 + lane;
                            float v = (col < M_COLS) ? S->lam[col] : -INFINITY;
                            if (v > a)       { bb = a; bj = aj; a = v; aj = col; }
                            else if (v > bb) { bb = v; bj = col; }
                        }
                        if (aj == i1) { m2 = bb; i2 = bj; }
                        else          { m2 = a;  i2 = aj; }
                    }
                }
            }
            __syncwarp();

            // ---- emit: lanes 0..24, one winner each (psi already decayed) ----
            if (lane < K_TOP) {
                int   c    = mycol;
                int   w    = (int)S->win[c];
                int   cell = c * N_CELLS + w;
                float y    = tanhf(S->sig[c]);
                float pd   = S->psi[cell];
                S->didx [lane] = cell;
                S->delta[lane] = fmaxf(y - pd, 0.f);
                S->psi[cell]   = fmaxf(pd, y);
                size_t o = ((size_t)t * B_SZ + b) * K_TOP + lane;
                g_ycidx[o] = c;
                g_ycval[o] = fmaxf(y, 0.f);
            }
        }
        __syncthreads();
    }
}

// ---------------- fused GEMM + scan kernel (scan blocks FIRST) ----------------
__global__ void __launch_bounds__(512, 2)
fused_gemm_scan(const float* __restrict__ x, const float* __restrict__ w_a)
{
    __shared__ __align__(16) char smem[sizeof(GemmSmem)];
    if (blockIdx.x < B_SZ) scan_part(smem, blockIdx.x);
    else                   gemm_part(x, w_a, smem, blockIdx.x - B_SZ);
}

// ---------------- sparse decode: out[tb] = b_d + sum_i y_i * w_dT[c_i] ----------
__global__ void __launch_bounds__(256) decode_kernel(const float* __restrict__ b_d,
                                                     float* __restrict__ out)
{
    const int tb  = blockIdx.x;
    const int tid = threadIdx.x;

    __shared__ int   s_c[K_TOP];
    __shared__ float s_y[K_TOP];
    if (tid < K_TOP) {
        s_c[tid] = g_ycidx[(size_t)tb * K_TOP + tid];
        s_y[tid] = g_ycval[(size_t)tb * K_TOP + tid];
    }
    __syncthreads();

    float4 acc = *reinterpret_cast<const float4*>(&b_d[tid * 4]);
#pragma unroll
    for (int i = 0; i < K_TOP; i++) {
        float y = s_y[i];
        const float4 w = *reinterpret_cast<const float4*>(
            &g_wdt[(size_t)s_c[i] * D_OUT + tid * 4]);
        acc.x = fmaf(y, w.x, acc.x);
        acc.y = fmaf(y, w.y, acc.y);
        acc.z = fmaf(y, w.z, acc.z);
        acc.w = fmaf(y, w.w, acc.w);
    }
    *reinterpret_cast<float4*>(&out[(size_t)tb * D_OUT + tid * 4]) = acc;
}

// ---------------- host launch ----------------
extern "C" void kernel_launch(void* const* d_in, const int* in_sizes, int n_in,
                              void* d_out, int out_size)
{
    const float* x   = (const float*)d_in[0];   // [T, B, D_IN]
    const float* w_a = (const float*)d_in[1];   // [M, D_IN]
    const float* w_b = (const float*)d_in[2];   // [TC, TC]
    const float* w_d = (const float*)d_in[3];   // [D_OUT, M]
    const float* b_d = (const float*)d_in[4];   // [D_OUT]
    float* out = (float*)d_out;                 // [T, B, D_OUT]

    float *wbt, *wdt;
    cudaGetSymbolAddress((void**)&wbt, g_wbt);
    cudaGetSymbolAddress((void**)&wdt, g_wdt);

    zero_cnt_kernel<<<1, 64>>>();

    transpose_kernel<<<dim3(TC / 32, TC / 32), dim3(32, 8)>>>(w_b, wbt, TC, TC);
    transpose_kernel<<<dim3((M_COLS + 31) / 32, D_OUT / 32), dim3(32, 8)>>>(
        w_d, wdt, D_OUT, M_COLS);

    fused_gemm_scan<<<B_SZ + GEMM_BLOCKS, 512>>>(x, w_a);

    decode_kernel<<<T_STEPS * B_SZ, 256>>>(b_d, out);
}

// round 15
// speedup vs baseline: 1.5292x; 1.4838x over previous
#include <cuda_runtime.h>
#include <math.h>

// ---------------- problem constants ----------------
#define T_STEPS 64
#define B_SZ    128
#define M_COLS  1000
#define N_CELLS 4
#define TC      4000      // M_COLS * N_CELLS
#define K_TOP   25
#define D_IN    1024
#define D_OUT   1024
#define GEMM_BLOCKS 512   // 64 timesteps x 8 column tiles

// ---------------- persistent device state ----------------
__device__ float g_za_all[T_STEPS * B_SZ * M_COLS]; // feedforward drive
__device__ float g_wbt  [TC * TC];                  // w_b transposed
__device__ float g_wdt  [M_COLS * D_OUT];           // w_d transposed
__device__ int   g_ycidx[T_STEPS * B_SZ * K_TOP];   // selected columns per (t,b)
__device__ float g_ycval[T_STEPS * B_SZ * K_TOP];   // max(y,0) per (t,b)
__device__ int   g_cnt  [T_STEPS];                  // za readiness counters

// ---------------- init (counters must reset every graph replay) ----------------
__global__ void zero_cnt_kernel() {
    if (threadIdx.x < T_STEPS) g_cnt[threadIdx.x] = 0;
}

// ---------------- generic 32x32 tiled transpose with bounds ----------------
__global__ void transpose_kernel(const float* __restrict__ in, float* __restrict__ out,
                                 int rows, int cols)
{
    __shared__ float tile[32][33];
    int c0 = blockIdx.x * 32, r0 = blockIdx.y * 32;
#pragma unroll
    for (int j = 0; j < 32; j += 8) {
        int r = r0 + threadIdx.y + j, c = c0 + threadIdx.x;
        if (r < rows && c < cols)
            tile[threadIdx.y + j][threadIdx.x] = in[(size_t)r * cols + c];
    }
    __syncthreads();
#pragma unroll
    for (int j = 0; j < 32; j += 8) {
        int c = c0 + threadIdx.y + j, r = r0 + threadIdx.x;
        if (r < rows && c < cols)
            out[(size_t)c * rows + r] = tile[threadIdx.x][threadIdx.y + j];
    }
}

// ---------------- shared memory overlays ----------------
struct GemmSmem {                       // 34,304 B
    float As[2][16][128 + 4];
    float Bs[2][16][128 + 8];
};
struct ScanSmem {                       // ~29.2 KB
    float         psi[TC];
    float         lam[M_COLS];
    float         sig[M_COLS];
    unsigned char win[M_COLS];
    int           didx [K_TOP];
    float         delta[K_TOP];
};

// ---------------- GEMM part: one 128x128 za tile, then signal ----------------
__device__ void gemm_part(const float* __restrict__ x, const float* __restrict__ w_a,
                          char* smem, int gbid)
{
    GemmSmem* S = reinterpret_cast<GemmSmem*>(smem);
    const int t   = gbid >> 3;
    const int n0  = (gbid & 7) * 128;
    const int tid = threadIdx.x;
    const int tn  = tid & 31;
    const int tm  = tid >> 5;
    const int arow = tid >> 2, aq = tid & 3;

    const float* A = x + (size_t)t * B_SZ * D_IN;
    float*       C = g_za_all + (size_t)t * B_SZ * M_COLS;

    unsigned long long acc[8][2];
#pragma unroll
    for (int i = 0; i < 8; i++) { acc[i][0] = 0ull; acc[i][1] = 0ull; }

    float4 aR = *reinterpret_cast<const float4*>(&A[(size_t)arow * D_IN + aq * 4]);
    float4 bR = make_float4(0.f, 0.f, 0.f, 0.f);
    if (n0 + arow < M_COLS)
        bR = *reinterpret_cast<const float4*>(&w_a[(size_t)(n0 + arow) * D_IN + aq * 4]);
    {
        S->As[0][aq * 4 + 0][arow] = aR.x; S->As[0][aq * 4 + 1][arow] = aR.y;
        S->As[0][aq * 4 + 2][arow] = aR.z; S->As[0][aq * 4 + 3][arow] = aR.w;
        S->Bs[0][aq * 4 + 0][arow] = bR.x; S->Bs[0][aq * 4 + 1][arow] = bR.y;
        S->Bs[0][aq * 4 + 2][arow] = bR.z; S->Bs[0][aq * 4 + 3][arow] = bR.w;
    }
    __syncthreads();

    const int nk = D_IN / 16;
    for (int kt = 0; kt < nk; kt++) {
        const int buf = kt & 1;
        if (kt + 1 < nk) {
            int kb = (kt + 1) * 16;
            aR = *reinterpret_cast<const float4*>(&A[(size_t)arow * D_IN + kb + aq * 4]);
            bR = make_float4(0.f, 0.f, 0.f, 0.f);
            if (n0 + arow < M_COLS)
                bR = *reinterpret_cast<const float4*>(&w_a[(size_t)(n0 + arow) * D_IN + kb + aq * 4]);
        }
#pragma unroll
        for (int k = 0; k < 16; k++) {
            float4 a0 = *reinterpret_cast<const float4*>(&S->As[buf][k][tm * 8]);
            float4 a1 = *reinterpret_cast<const float4*>(&S->As[buf][k][tm * 8 + 4]);
            const unsigned long long* bp =
                reinterpret_cast<const unsigned long long*>(&S->Bs[buf][k][tn * 4]);
            unsigned long long b2[2] = {bp[0], bp[1]};
            float av[8] = {a0.x, a0.y, a0.z, a0.w, a1.x, a1.y, a1.z, a1.w};
#pragma unroll
            for (int i = 0; i < 8; i++) {
                unsigned int au = __float_as_uint(av[i]);
                unsigned long long ap;
                asm("mov.b64 %0, {%1, %1};" : "=l"(ap) : "r"(au));
                asm("fma.rn.f32x2 %0, %1, %2, %0;" : "+l"(acc[i][0]) : "l"(ap), "l"(b2[0]));
                asm("fma.rn.f32x2 %0, %1, %2, %0;" : "+l"(acc[i][1]) : "l"(ap), "l"(b2[1]));
            }
        }
        if (kt + 1 < nk) {
            const int nb = buf ^ 1;
            S->As[nb][aq * 4 + 0][arow] = aR.x; S->As[nb][aq * 4 + 1][arow] = aR.y;
            S->As[nb][aq * 4 + 2][arow] = aR.z; S->As[nb][aq * 4 + 3][arow] = aR.w;
            S->Bs[nb][aq * 4 + 0][arow] = bR.x; S->Bs[nb][aq * 4 + 1][arow] = bR.y;
            S->Bs[nb][aq * 4 + 2][arow] = bR.z; S->Bs[nb][aq * 4 + 3][arow] = bR.w;
            __syncthreads();
        }
    }

#pragma unroll
    for (int i = 0; i < 8; i++) {
        int gm = tm * 8 + i;
#pragma unroll
        for (int j = 0; j < 2; j++) {
            unsigned int lo, hi;
            asm("mov.b64 {%0, %1}, %2;" : "=r"(lo), "=r"(hi) : "l"(acc[i][j]));
            int gn = n0 + tn * 4 + 2 * j;
            if (gn < M_COLS)     C[(size_t)gm * M_COLS + gn]     = __uint_as_float(lo);
            if (gn + 1 < M_COLS) C[(size_t)gm * M_COLS + gn + 1] = __uint_as_float(hi);
        }
    }

    __threadfence();
    __syncthreads();
    if (threadIdx.x == 0) atomicAdd(&g_cnt[t], 1);
}

// ---------------- scan part: R9 structure, butterfly top-k + top-3 cache ------
__device__ void scan_part(char* smem, int b)
{
    ScanSmem* S = reinterpret_cast<ScanSmem*>(smem);
    const int tid    = threadIdx.x;
    const int lane   = tid & 31;
    const int warpid = tid >> 5;

    const int c0 = tid;                // column 0..511
    const int c1 = tid + 512;          // column 512..1023 (valid < 1000)
    const bool two = (c1 < M_COLS);

    float4 z0 = make_float4(0.f, 0.f, 0.f, 0.f);
    float4 z1 = make_float4(0.f, 0.f, 0.f, 0.f);

    for (int i = tid; i < TC; i += 512) S->psi[i] = 0.f;
    __syncthreads();

    for (int t = 0; t < T_STEPS; t++) {
        // wait for za[t] (8 tiles)
        if (tid == 0) {
            unsigned int v;
            do {
                asm volatile("ld.acquire.gpu.u32 %0, [%1];"
                             : "=r"(v) : "l"(&g_cnt[t]) : "memory");
            } while (v < 8u);
        }
        __syncthreads();

        // ---- fused: rank-25 z_b update (t>0), fully unrolled (high MLP) ----
        if (t > 0) {
            float4 a0 = make_float4(0.5f * z0.x, 0.5f * z0.y, 0.5f * z0.z, 0.5f * z0.w);
            float4 a1 = make_float4(0.5f * z1.x, 0.5f * z1.y, 0.5f * z1.z, 0.5f * z1.w);
#pragma unroll
            for (int i = 0; i < K_TOP; i++) {
                float d = S->delta[i];
                const float* base = &g_wbt[(size_t)S->didx[i] * TC];
                float4 w0 = *reinterpret_cast<const float4*>(&base[c0 * 4]);
                a0.x = fmaf(d, w0.x, a0.x); a0.y = fmaf(d, w0.y, a0.y);
                a0.z = fmaf(d, w0.z, a0.z); a0.w = fmaf(d, w0.w, a0.w);
                if (two) {
                    float4 w1 = *reinterpret_cast<const float4*>(&base[c1 * 4]);
                    a1.x = fmaf(d, w1.x, a1.x); a1.y = fmaf(d, w1.y, a1.y);
                    a1.z = fmaf(d, w1.z, a1.z); a1.w = fmaf(d, w1.w, a1.w);
                }
            }
            z0 = a0; z1 = a1;
        }

        // ---- phase A: winner cell + column max of pi + psi decay ----
        const float* zab = g_za_all + ((size_t)t * B_SZ + b) * M_COLS;
#pragma unroll
        for (int h = 0; h < 2; h++) {
            int c = (h == 0) ? c0 : c1;
            if (h == 1 && !two) break;
            float4 z = (h == 0) ? z0 : z1;
            float  zac = __ldcg(&zab[c]);
            float4 ph  = *reinterpret_cast<const float4*>(&S->psi[c * 4]);
            float sig[4] = {zac + z.x, zac + z.y, zac + z.z, zac + z.w};
            float pv [4] = {sig[0] * (1.f - ph.x), sig[1] * (1.f - ph.y),
                            sig[2] * (1.f - ph.z), sig[3] * (1.f - ph.w)};
            float best = pv[0]; int bw = 0;
#pragma unroll
            for (int n = 1; n < N_CELLS; n++)
                if (pv[n] > best) { best = pv[n]; bw = n; }
            S->lam[c] = best;
            S->win[c] = (unsigned char)bw;
            S->sig[c] = sig[bw];
            *reinterpret_cast<float4*>(&S->psi[c * 4]) =
                make_float4(0.5f * ph.x, 0.5f * ph.y, 0.5f * ph.z, 0.5f * ph.w);
        }
        __syncthreads();

        // ---- top-K by warp 0: butterfly extraction + per-lane top-3 cache ----
        if (warpid == 0) {
            float v[32];
#pragma unroll
            for (int j = 0; j < 32; j++) {
                int col = j * 32 + lane;
                v[j] = (col < M_COLS) ? S->lam[col] : -INFINITY;
            }
            // build per-lane top-3 (value desc; first index kept on ties)
            float m1 = -INFINITY, m2 = -INFINITY, m3 = -INFINITY;
            int   i1 = 0x7fffffff, i2 = 0x7fffffff, i3 = 0x7fffffff;
#pragma unroll
            for (int j = 0; j < 32; j++) {
                float val = v[j]; int col = j * 32 + lane;
                if (val > m1)      { m3 = m2; i3 = i2; m2 = m1; i2 = i1; m1 = val; i1 = col; }
                else if (val > m2) { m3 = m2; i3 = i2; m2 = val; i2 = col; }
                else if (val > m3) { m3 = val; i3 = col; }
            }
            int navail = 3;
            int mycol  = 0;

            for (int it = 0; it < K_TOP; it++) {
                float bv = m1; int bc = i1;
#pragma unroll
                for (int off = 16; off > 0; off >>= 1) {
                    float ov = __shfl_xor_sync(0xffffffffu, bv, off);
                    int   oc = __shfl_xor_sync(0xffffffffu, bc, off);
                    if (ov > bv || (ov == bv && oc < bc)) { bv = ov; bc = oc; }
                }
                if (lane == it) mycol = bc;
                if ((bc & 31) == lane) {           // owning lane: pop cache
                    v[bc >> 5] = -INFINITY;
                    m1 = m2; i1 = i2;
                    m2 = m3; i2 = i3;
                    m3 = -INFINITY; i3 = 0x7fffffff;
                    navail--;
                    if (navail == 0 && it < K_TOP - 1) {   // rare: rebuild top-3
                        m1 = -INFINITY; m2 = -INFINITY; m3 = -INFINITY;
                        i1 = 0x7fffffff; i2 = 0x7fffffff; i3 = 0x7fffffff;
#pragma unroll
                        for (int j = 0; j < 32; j++) {
                            float val = v[j]; int col = j * 32 + lane;
                            if (val > m1)      { m3 = m2; i3 = i2; m2 = m1; i2 = i1; m1 = val; i1 = col; }
                            else if (val > m2) { m3 = m2; i3 = i2; m2 = val; i2 = col; }
                            else if (val > m3) { m3 = val; i3 = col; }
                        }
                        navail = 3;
                    }
                }
            }
            __syncwarp();

            // ---- emit: lanes 0..24, one winner each (psi already decayed) ----
            if (lane < K_TOP) {
                int   c    = mycol;
                int   w    = (int)S->win[c];
                int   cell = c * N_CELLS + w;
                float y    = tanhf(S->sig[c]);
                float pd   = S->psi[cell];
                S->didx [lane] = cell;
                S->delta[lane] = fmaxf(y - pd, 0.f);
                S->psi[cell]   = fmaxf(pd, y);
                size_t o = ((size_t)t * B_SZ + b) * K_TOP + lane;
                g_ycidx[o] = c;
                g_ycval[o] = fmaxf(y, 0.f);
            }
        }
        __syncthreads();
    }
}

// ---------------- fused GEMM + scan kernel (scan blocks FIRST) ----------------
__global__ void __launch_bounds__(512, 2)
fused_gemm_scan(const float* __restrict__ x, const float* __restrict__ w_a)
{
    __shared__ __align__(16) char smem[sizeof(GemmSmem)];
    if (blockIdx.x < B_SZ) scan_part(smem, blockIdx.x);
    else                   gemm_part(x, w_a, smem, blockIdx.x - B_SZ);
}

// ---------------- sparse decode: out[tb] = b_d + sum_i y_i * w_dT[c_i] ----------
__global__ void __launch_bounds__(256) decode_kernel(const float* __restrict__ b_d,
                                                     float* __restrict__ out)
{
    const int tb  = blockIdx.x;
    const int tid = threadIdx.x;

    __shared__ int   s_c[K_TOP];
    __shared__ float s_y[K_TOP];
    if (tid < K_TOP) {
        s_c[tid] = g_ycidx[(size_t)tb * K_TOP + tid];
        s_y[tid] = g_ycval[(size_t)tb * K_TOP + tid];
    }
    __syncthreads();

    float4 acc = *reinterpret_cast<const float4*>(&b_d[tid * 4]);
#pragma unroll
    for (int i = 0; i < K_TOP; i++) {
        float y = s_y[i];
        const float4 w = *reinterpret_cast<const float4*>(
            &g_wdt[(size_t)s_c[i] * D_OUT + tid * 4]);
        acc.x = fmaf(y, w.x, acc.x);
        acc.y = fmaf(y, w.y, acc.y);
        acc.z = fmaf(y, w.z, acc.z);
        acc.w = fmaf(y, w.w, acc.w);
    }
    *reinterpret_cast<float4*>(&out[(size_t)tb * D_OUT + tid * 4]) = acc;
}

// ---------------- host launch ----------------
extern "C" void kernel_launch(void* const* d_in, const int* in_sizes, int n_in,
                              void* d_out, int out_size)
{
    const float* x   = (const float*)d_in[0];   // [T, B, D_IN]
    const float* w_a = (const float*)d_in[1];   // [M, D_IN]
    const float* w_b = (const float*)d_in[2];   // [TC, TC]
    const float* w_d = (const float*)d_in[3];   // [D_OUT, M]
    const float* b_d = (const float*)d_in[4];   // [D_OUT]
    float* out = (float*)d_out;                 // [T, B, D_OUT]

    float *wbt, *wdt;
    cudaGetSymbolAddress((void**)&wbt, g_wbt);
    cudaGetSymbolAddress((void**)&wdt, g_wdt);

    zero_cnt_kernel<<<1, 64>>>();

    transpose_kernel<<<dim3(TC / 32, TC / 32), dim3(32, 8)>>>(w_b, wbt, TC, TC);
    transpose_kernel<<<dim3((M_COLS + 31) / 32, D_OUT / 32), dim3(32, 8)>>>(
        w_d, wdt, D_OUT, M_COLS);

    fused_gemm_scan<<<B_SZ + GEMM_BLOCKS, 512>>>(x, w_a);

    decode_kernel<<<T_STEPS * B_SZ, 256>>>(b_d, out);
}